// round 6
// baseline (speedup 1.0000x reference)
#include <cuda_runtime.h>

// ---------------------------------------------------------------------------
// PC_RNN_HC_A: 512-step predictive-coding RNN scan.
// Single persistent kernel, 128 CTAs (all co-resident on 148/152-SM sm_103a),
// hand-rolled grid barrier, fp32 SIMT tiled GEMMs, weights L2-resident.
// ---------------------------------------------------------------------------

#define GRID      128
#define NTHREADS  256

#define SEQ   512
#define BATCH 256
#define OUTD  256
#define CAUS  64
#define HID   512

#define SA 72   // smem stride for k-major tiles (KC=64 + 8 pad), 288B = 16*18 aligned

// Persistent state (device globals: no allocation allowed)
__device__ float g_h [BATCH * HID];   // h_post
__device__ float g_th[BATCH * HID];   // tanh(h_post)
__device__ float g_hp[BATCH * HID];   // h_prior
__device__ float g_tp[BATCH * HID];   // tanh(h_prior)
__device__ float g_eh[BATCH * HID];   // error_h
__device__ float g_err[BATCH * OUTD];
__device__ float g_c [BATCH * CAUS];

__device__ unsigned g_bar_count;      // zero-initialized at module load
__device__ unsigned g_bar_gen;

// ---------------------------------------------------------------------------
// Grid-wide barrier (sense via monotone generation counter).
// Safe because grid (128) <= SM count and occupancy >= 1 CTA/SM, so every CTA
// is resident. Generation survives graph replays (relative compare).
// ---------------------------------------------------------------------------
__device__ __forceinline__ void grid_sync() {
    __syncthreads();
    if (threadIdx.x == 0) {
        volatile unsigned* genp = &g_bar_gen;
        unsigned my = *genp;               // read BEFORE arriving (stable: no one can release yet)
        __threadfence();                   // release all this CTA's prior writes
        unsigned prev = atomicAdd(&g_bar_count, 1u);
        if (prev == GRID - 1u) {
            g_bar_count = 0u;
            __threadfence();
            atomicExch(&g_bar_gen, my + 1u);
        } else {
            while (*genp == my) { }
            __threadfence();               // acquire
        }
    }
    __syncthreads();
}

// ---------------------------------------------------------------------------
// Shared-memory loaders. KC = 64 always.
// k-major: tile of T rows x 64 k, from G[row][k] (row-major, ld = ldg).
// ---------------------------------------------------------------------------
template<int T>
__device__ __forceinline__ void load_kmajor(float* s, const float* __restrict__ G,
                                            int ldg, int k0) {
    const int tid = threadIdx.x;
#pragma unroll
    for (int it = 0; it < (T * 16) / NTHREADS; it++) {
        int idx = tid + it * NTHREADS;
        int row = idx >> 4;
        int k4  = idx & 15;
        *reinterpret_cast<float4*>(s + row * SA + k4 * 4) =
            *reinterpret_cast<const float4*>(G + row * ldg + k0 + k4 * 4);
    }
}

// n-major: tile of 64 k x TN cols, from G[k][n] (row-major, ld = ldg), stored as
// b_s[k][n] with stride SN = TN+8 (keeps 16B alignment + bank phase shift).
template<int TN>
__device__ __forceinline__ void load_nmajor(float* s, const float* __restrict__ G,
                                            int ldg, int k0) {
    constexpr int N4 = TN / 4;
    constexpr int SN = TN + 8;
    const int tid = threadIdx.x;
#pragma unroll
    for (int it = 0; it < (64 * N4) / NTHREADS; it++) {
        int idx = tid + it * NTHREADS;
        int k   = idx / N4;
        int n4  = idx - k * N4;
        *reinterpret_cast<float4*>(s + k * SN + n4 * 4) =
            *reinterpret_cast<const float4*>(G + (k0 + k) * ldg + n4 * 4);
    }
}

// ---------------------------------------------------------------------------
// NT GEMM: acc[m][n] += sum_k A[m][k] * Bm[n][k]   (both operands k-major)
// Thread layout: tx = tid&15 (cols), ty = tid>>4 (rows); 2x2 reps max.
// ---------------------------------------------------------------------------
template<int TM, int TN>
__device__ __forceinline__ void gemm_nt(float* a_s, float* b_s,
                                        const float* __restrict__ A, int lda,
                                        const float* __restrict__ Bm, int ldb,
                                        int K, float (&acc)[TM / 16][TN / 16]) {
    constexpr int RM = TM / 16, RN = TN / 16;
    const int tx = threadIdx.x & 15, ty = threadIdx.x >> 4;
    for (int k0 = 0; k0 < K; k0 += 64) {
        load_kmajor<TM>(a_s, A, lda, k0);
        load_kmajor<TN>(b_s, Bm, ldb, k0);
        __syncthreads();
#pragma unroll
        for (int k4 = 0; k4 < 16; k4++) {
            float4 av[RM], bv[RN];
#pragma unroll
            for (int im = 0; im < RM; im++)
                av[im] = *reinterpret_cast<const float4*>(a_s + (ty + 16 * im) * SA + k4 * 4);
#pragma unroll
            for (int in = 0; in < RN; in++)
                bv[in] = *reinterpret_cast<const float4*>(b_s + (tx + 16 * in) * SA + k4 * 4);
#pragma unroll
            for (int im = 0; im < RM; im++)
#pragma unroll
                for (int in = 0; in < RN; in++) {
                    acc[im][in] += av[im].x * bv[in].x;
                    acc[im][in] += av[im].y * bv[in].y;
                    acc[im][in] += av[im].z * bv[in].z;
                    acc[im][in] += av[im].w * bv[in].w;
                }
        }
        __syncthreads();
    }
}

// ---------------------------------------------------------------------------
// NN GEMM: acc[m][n] += sum_k A[m][k] * Bn[k][n]   (B is n-major in global)
// ---------------------------------------------------------------------------
template<int TM, int TN>
__device__ __forceinline__ void gemm_nn(float* a_s, float* b_s,
                                        const float* __restrict__ A, int lda,
                                        const float* __restrict__ Bn, int ldb,
                                        int K, float (&acc)[TM / 16][TN / 16]) {
    constexpr int RM = TM / 16, RN = TN / 16;
    constexpr int SN = TN + 8;
    const int tx = threadIdx.x & 15, ty = threadIdx.x >> 4;
    for (int k0 = 0; k0 < K; k0 += 64) {
        load_kmajor<TM>(a_s, A, lda, k0);
        load_nmajor<TN>(b_s, Bn, ldb, k0);
        __syncthreads();
#pragma unroll
        for (int k4 = 0; k4 < 16; k4++) {
            float av[RM][4];
#pragma unroll
            for (int im = 0; im < RM; im++)
                *reinterpret_cast<float4*>(av[im]) =
                    *reinterpret_cast<const float4*>(a_s + (ty + 16 * im) * SA + k4 * 4);
#pragma unroll
            for (int kk = 0; kk < 4; kk++) {
                float bb[RN];
#pragma unroll
                for (int in = 0; in < RN; in++)
                    bb[in] = b_s[(k4 * 4 + kk) * SN + tx + 16 * in];
#pragma unroll
                for (int im = 0; im < RM; im++)
#pragma unroll
                    for (int in = 0; in < RN; in++)
                        acc[im][in] += av[im][kk] * bb[in];
            }
        }
        __syncthreads();
    }
}

// ---------------------------------------------------------------------------
// Main persistent kernel
// ---------------------------------------------------------------------------
__global__ void __launch_bounds__(NTHREADS)
pc_rnn_kernel(const float* __restrict__ x,
              const float* __restrict__ c_init,
              const float* __restrict__ h_init,
              const float* __restrict__ w_o,
              const float* __restrict__ b_o,
              const float* __restrict__ w_c,
              const float* __restrict__ w_r,
              const float* __restrict__ b_r,
              float* __restrict__ out) {
    __shared__ float a_s[32 * SA];   // 2304 floats
    __shared__ float b_s[2560];      // max(32*SA, 64*(32+8))

    const int bid = blockIdx.x;
    const int tid = threadIdx.x;
    const int tx  = tid & 15, ty = tid >> 4;
    const int gtid = bid * NTHREADS + tid;
    const int gstride = GRID * NTHREADS;

    // ---- init state from inputs (fresh every launch / graph replay) ----
    for (int i = gtid; i < BATCH * HID; i += gstride) {
        float h = h_init[i];
        g_h[i]  = h;
        g_th[i] = tanhf(h);
    }
    for (int i = gtid; i < BATCH * CAUS; i += gstride)
        g_c[i] = c_init[i];
    grid_sync();

    for (int t = 0; t < SEQ; t++) {
        // ---- Phase A: h_prior = 0.9*h + 0.1*(th@Wr^T + c@Wc^T + b_r); tp = tanh ----
        // out 256x512: 8x16 tiles of 32x32 -> 128 CTAs exactly
        {
            const int tr = bid >> 4, tc = bid & 15;
            const int row0 = tr * 32, col0 = tc * 32;
            float acc[2][2] = {};
            gemm_nt<32, 32>(a_s, b_s, g_th + row0 * HID, HID,
                            w_r + col0 * HID, HID, HID, acc);
            gemm_nt<32, 32>(a_s, b_s, g_c + row0 * CAUS, CAUS,
                            w_c + col0 * CAUS, CAUS, CAUS, acc);
#pragma unroll
            for (int im = 0; im < 2; im++)
#pragma unroll
                for (int in = 0; in < 2; in++) {
                    int r  = row0 + ty + 16 * im;
                    int ci = col0 + tx + 16 * in;
                    int idx = r * HID + ci;
                    float hp = 0.9f * g_h[idx] + 0.1f * (acc[im][in] + b_r[ci]);
                    g_hp[idx] = hp;
                    g_tp[idx] = tanhf(hp);
                }
        }
        grid_sync();

        // ---- Phase B: err = tp@Wo^T + b_o - x_t  (also streamed to out) ----
        // out 256x256: 16x8 tiles of 16x32 -> 128 CTAs exactly
        {
            const int tr = bid >> 3, tc = bid & 7;
            const int row0 = tr * 16, col0 = tc * 32;
            float acc[1][2] = {};
            gemm_nt<16, 32>(a_s, b_s, g_tp + row0 * HID, HID,
                            w_o + col0 * HID, HID, HID, acc);
            const int r = row0 + ty;
#pragma unroll
            for (int in = 0; in < 2; in++) {
                int o  = col0 + tx + 16 * in;
                int xi = (t * BATCH + r) * OUTD + o;
                float e = acc[0][in] + b_o[o] - x[xi];
                g_err[r * OUTD + o] = e;
                out[xi] = e;
            }
        }
        grid_sync();

        // ---- Phase C: g = err@Wo; eh = 0.1*(1-tp^2)*g; h_post = h_prior - eh ----
        // out 256x512: 8x16 tiles of 32x32 -> 128 CTAs exactly; B is n-major (Wo[o][i])
        {
            const int tr = bid >> 4, tc = bid & 15;
            const int row0 = tr * 32, col0 = tc * 32;
            float acc[2][2] = {};
            gemm_nn<32, 32>(a_s, b_s, g_err + row0 * OUTD, OUTD,
                            w_o + col0, HID, OUTD, acc);
#pragma unroll
            for (int im = 0; im < 2; im++)
#pragma unroll
                for (int in = 0; in < 2; in++) {
                    int r  = row0 + ty + 16 * im;
                    int ci = col0 + tx + 16 * in;
                    int idx = r * HID + ci;
                    float tp = g_tp[idx];
                    float eh = 0.1f * (1.0f - tp * tp) * acc[im][in];
                    float hpost = g_hp[idx] - eh;
                    g_eh[idx] = eh;
                    g_h[idx]  = hpost;
                    g_th[idx] = tanhf(hpost);
                }
        }
        grid_sync();

        // ---- Phase D: c -= 0.1 * (eh @ Wc) ----
        // out 256x64: 16x4 tiles of 16x16 -> 64 CTAs; B n-major (Wc[i][k])
        if (bid < 64) {
            const int tr = bid >> 2, tc = bid & 3;
            const int row0 = tr * 16, col0 = tc * 16;
            float acc[1][1] = {};
            gemm_nn<16, 16>(a_s, b_s, g_eh + row0 * HID, HID,
                            w_c + col0, CAUS, HID, acc);
            const int r = row0 + ty;
            const int kc = col0 + tx;
            g_c[r * CAUS + kc] -= 0.1f * acc[0][0];
        }
        grid_sync();
    }
}

// ---------------------------------------------------------------------------
// Launch: single kernel node, graph-capturable, no allocation.
// Inputs (metadata order): x, c_init, h_init, w_o, b_o, w_c, w_r, b_r
// ---------------------------------------------------------------------------
extern "C" void kernel_launch(void* const* d_in, const int* in_sizes, int n_in,
                              void* d_out, int out_size) {
    const float* x      = (const float*)d_in[0];
    const float* c_init = (const float*)d_in[1];
    const float* h_init = (const float*)d_in[2];
    const float* w_o    = (const float*)d_in[3];
    const float* b_o    = (const float*)d_in[4];
    const float* w_c    = (const float*)d_in[5];
    const float* w_r    = (const float*)d_in[6];
    const float* b_r    = (const float*)d_in[7];
    float* out = (float*)d_out;

    pc_rnn_kernel<<<GRID, NTHREADS>>>(x, c_init, h_init, w_o, b_o, w_c, w_r, b_r, out);
}

// round 7
// speedup vs baseline: 1.0009x; 1.0009x over previous
#include <cuda_runtime.h>

// ---------------------------------------------------------------------------
// PC_RNN_HC_A: 512-step predictive-coding RNN scan.
// Single persistent kernel, 128 CTAs (all co-resident on 148/152-SM sm_103a),
// hand-rolled grid barrier, fp32 SIMT tiled GEMMs, weights L2-resident.
// ---------------------------------------------------------------------------

#define GRID      128
#define NTHREADS  256

#define SEQ   512
#define BATCH 256
#define OUTD  256
#define CAUS  64
#define HID   512

#define SA 72   // smem stride for k-major tiles (KC=64 + 8 pad), 288B = 16*18 aligned

// Persistent state (device globals: no allocation allowed)
__device__ float g_h [BATCH * HID];   // h_post
__device__ float g_th[BATCH * HID];   // tanh(h_post)
__device__ float g_hp[BATCH * HID];   // h_prior
__device__ float g_tp[BATCH * HID];   // tanh(h_prior)
__device__ float g_eh[BATCH * HID];   // error_h
__device__ float g_err[BATCH * OUTD];
__device__ float g_c [BATCH * CAUS];

__device__ unsigned g_bar_count;      // zero-initialized at module load
__device__ unsigned g_bar_gen;

// ---------------------------------------------------------------------------
// Grid-wide barrier (sense via monotone generation counter).
// Safe because grid (128) <= SM count and occupancy >= 1 CTA/SM, so every CTA
// is resident. Generation survives graph replays (relative compare).
// ---------------------------------------------------------------------------
__device__ __forceinline__ void grid_sync() {
    __syncthreads();
    if (threadIdx.x == 0) {
        volatile unsigned* genp = &g_bar_gen;
        unsigned my = *genp;               // read BEFORE arriving (stable: no one can release yet)
        __threadfence();                   // release all this CTA's prior writes
        unsigned prev = atomicAdd(&g_bar_count, 1u);
        if (prev == GRID - 1u) {
            g_bar_count = 0u;
            __threadfence();
            atomicExch(&g_bar_gen, my + 1u);
        } else {
            while (*genp == my) { }
            __threadfence();               // acquire
        }
    }
    __syncthreads();
}

// ---------------------------------------------------------------------------
// Shared-memory loaders. KC = 64 always.
// k-major: tile of T rows x 64 k, from G[row][k] (row-major, ld = ldg).
// ---------------------------------------------------------------------------
template<int T>
__device__ __forceinline__ void load_kmajor(float* s, const float* __restrict__ G,
                                            int ldg, int k0) {
    const int tid = threadIdx.x;
#pragma unroll
    for (int it = 0; it < (T * 16) / NTHREADS; it++) {
        int idx = tid + it * NTHREADS;
        int row = idx >> 4;
        int k4  = idx & 15;
        *reinterpret_cast<float4*>(s + row * SA + k4 * 4) =
            *reinterpret_cast<const float4*>(G + row * ldg + k0 + k4 * 4);
    }
}

// n-major: tile of 64 k x TN cols, from G[k][n] (row-major, ld = ldg), stored as
// b_s[k][n] with stride SN = TN+8 (keeps 16B alignment + bank phase shift).
template<int TN>
__device__ __forceinline__ void load_nmajor(float* s, const float* __restrict__ G,
                                            int ldg, int k0) {
    constexpr int N4 = TN / 4;
    constexpr int SN = TN + 8;
    const int tid = threadIdx.x;
#pragma unroll
    for (int it = 0; it < (64 * N4) / NTHREADS; it++) {
        int idx = tid + it * NTHREADS;
        int k   = idx / N4;
        int n4  = idx - k * N4;
        *reinterpret_cast<float4*>(s + k * SN + n4 * 4) =
            *reinterpret_cast<const float4*>(G + (k0 + k) * ldg + n4 * 4);
    }
}

// ---------------------------------------------------------------------------
// NT GEMM: acc[m][n] += sum_k A[m][k] * Bm[n][k]   (both operands k-major)
// Thread layout: tx = tid&15 (cols), ty = tid>>4 (rows); 2x2 reps max.
// ---------------------------------------------------------------------------
template<int TM, int TN>
__device__ __forceinline__ void gemm_nt(float* a_s, float* b_s,
                                        const float* __restrict__ A, int lda,
                                        const float* __restrict__ Bm, int ldb,
                                        int K, float (&acc)[TM / 16][TN / 16]) {
    constexpr int RM = TM / 16, RN = TN / 16;
    const int tx = threadIdx.x & 15, ty = threadIdx.x >> 4;
    for (int k0 = 0; k0 < K; k0 += 64) {
        load_kmajor<TM>(a_s, A, lda, k0);
        load_kmajor<TN>(b_s, Bm, ldb, k0);
        __syncthreads();
#pragma unroll
        for (int k4 = 0; k4 < 16; k4++) {
            float4 av[RM], bv[RN];
#pragma unroll
            for (int im = 0; im < RM; im++)
                av[im] = *reinterpret_cast<const float4*>(a_s + (ty + 16 * im) * SA + k4 * 4);
#pragma unroll
            for (int in = 0; in < RN; in++)
                bv[in] = *reinterpret_cast<const float4*>(b_s + (tx + 16 * in) * SA + k4 * 4);
#pragma unroll
            for (int im = 0; im < RM; im++)
#pragma unroll
                for (int in = 0; in < RN; in++) {
                    acc[im][in] += av[im].x * bv[in].x;
                    acc[im][in] += av[im].y * bv[in].y;
                    acc[im][in] += av[im].z * bv[in].z;
                    acc[im][in] += av[im].w * bv[in].w;
                }
        }
        __syncthreads();
    }
}

// ---------------------------------------------------------------------------
// NN GEMM: acc[m][n] += sum_k A[m][k] * Bn[k][n]   (B is n-major in global)
// ---------------------------------------------------------------------------
template<int TM, int TN>
__device__ __forceinline__ void gemm_nn(float* a_s, float* b_s,
                                        const float* __restrict__ A, int lda,
                                        const float* __restrict__ Bn, int ldb,
                                        int K, float (&acc)[TM / 16][TN / 16]) {
    constexpr int RM = TM / 16, RN = TN / 16;
    constexpr int SN = TN + 8;
    const int tx = threadIdx.x & 15, ty = threadIdx.x >> 4;
    for (int k0 = 0; k0 < K; k0 += 64) {
        load_kmajor<TM>(a_s, A, lda, k0);
        load_nmajor<TN>(b_s, Bn, ldb, k0);
        __syncthreads();
#pragma unroll
        for (int k4 = 0; k4 < 16; k4++) {
            float av[RM][4];
#pragma unroll
            for (int im = 0; im < RM; im++)
                *reinterpret_cast<float4*>(av[im]) =
                    *reinterpret_cast<const float4*>(a_s + (ty + 16 * im) * SA + k4 * 4);
#pragma unroll
            for (int kk = 0; kk < 4; kk++) {
                float bb[RN];
#pragma unroll
                for (int in = 0; in < RN; in++)
                    bb[in] = b_s[(k4 * 4 + kk) * SN + tx + 16 * in];
#pragma unroll
                for (int im = 0; im < RM; im++)
#pragma unroll
                    for (int in = 0; in < RN; in++)
                        acc[im][in] += av[im][kk] * bb[in];
            }
        }
        __syncthreads();
    }
}

// ---------------------------------------------------------------------------
// Main persistent kernel
// ---------------------------------------------------------------------------
__global__ void __launch_bounds__(NTHREADS)
pc_rnn_kernel(const float* __restrict__ x,
              const float* __restrict__ c_init,
              const float* __restrict__ h_init,
              const float* __restrict__ w_o,
              const float* __restrict__ b_o,
              const float* __restrict__ w_c,
              const float* __restrict__ w_r,
              const float* __restrict__ b_r,
              float* __restrict__ out) {
    __shared__ float a_s[32 * SA];   // 2304 floats
    __shared__ float b_s[2560];      // max(32*SA, 64*(32+8))

    const int bid = blockIdx.x;
    const int tid = threadIdx.x;
    const int tx  = tid & 15, ty = tid >> 4;
    const int gtid = bid * NTHREADS + tid;
    const int gstride = GRID * NTHREADS;

    // ---- init state from inputs (fresh every launch / graph replay) ----
    for (int i = gtid; i < BATCH * HID; i += gstride) {
        float h = h_init[i];
        g_h[i]  = h;
        g_th[i] = tanhf(h);
    }
    for (int i = gtid; i < BATCH * CAUS; i += gstride)
        g_c[i] = c_init[i];
    grid_sync();

    for (int t = 0; t < SEQ; t++) {
        // ---- Phase A: h_prior = 0.9*h + 0.1*(th@Wr^T + c@Wc^T + b_r); tp = tanh ----
        // out 256x512: 8x16 tiles of 32x32 -> 128 CTAs exactly
        {
            const int tr = bid >> 4, tc = bid & 15;
            const int row0 = tr * 32, col0 = tc * 32;
            float acc[2][2] = {};
            gemm_nt<32, 32>(a_s, b_s, g_th + row0 * HID, HID,
                            w_r + col0 * HID, HID, HID, acc);
            gemm_nt<32, 32>(a_s, b_s, g_c + row0 * CAUS, CAUS,
                            w_c + col0 * CAUS, CAUS, CAUS, acc);
#pragma unroll
            for (int im = 0; im < 2; im++)
#pragma unroll
                for (int in = 0; in < 2; in++) {
                    int r  = row0 + ty + 16 * im;
                    int ci = col0 + tx + 16 * in;
                    int idx = r * HID + ci;
                    float hp = 0.9f * g_h[idx] + 0.1f * (acc[im][in] + b_r[ci]);
                    g_hp[idx] = hp;
                    g_tp[idx] = tanhf(hp);
                }
        }
        grid_sync();

        // ---- Phase B: err = tp@Wo^T + b_o - x_t  (also streamed to out) ----
        // out 256x256: 16x8 tiles of 16x32 -> 128 CTAs exactly
        {
            const int tr = bid >> 3, tc = bid & 7;
            const int row0 = tr * 16, col0 = tc * 32;
            float acc[1][2] = {};
            gemm_nt<16, 32>(a_s, b_s, g_tp + row0 * HID, HID,
                            w_o + col0 * HID, HID, HID, acc);
            const int r = row0 + ty;
#pragma unroll
            for (int in = 0; in < 2; in++) {
                int o  = col0 + tx + 16 * in;
                int xi = (t * BATCH + r) * OUTD + o;
                float e = acc[0][in] + b_o[o] - x[xi];
                g_err[r * OUTD + o] = e;
                out[xi] = e;
            }
        }
        grid_sync();

        // ---- Phase C: g = err@Wo; eh = 0.1*(1-tp^2)*g; h_post = h_prior - eh ----
        // out 256x512: 8x16 tiles of 32x32 -> 128 CTAs exactly; B is n-major (Wo[o][i])
        {
            const int tr = bid >> 4, tc = bid & 15;
            const int row0 = tr * 32, col0 = tc * 32;
            float acc[2][2] = {};
            gemm_nn<32, 32>(a_s, b_s, g_err + row0 * OUTD, OUTD,
                            w_o + col0, HID, OUTD, acc);
#pragma unroll
            for (int im = 0; im < 2; im++)
#pragma unroll
                for (int in = 0; in < 2; in++) {
                    int r  = row0 + ty + 16 * im;
                    int ci = col0 + tx + 16 * in;
                    int idx = r * HID + ci;
                    float tp = g_tp[idx];
                    float eh = 0.1f * (1.0f - tp * tp) * acc[im][in];
                    float hpost = g_hp[idx] - eh;
                    g_eh[idx] = eh;
                    g_h[idx]  = hpost;
                    g_th[idx] = tanhf(hpost);
                }
        }
        grid_sync();

        // ---- Phase D: c -= 0.1 * (eh @ Wc) ----
        // out 256x64: 16x4 tiles of 16x16 -> 64 CTAs; B n-major (Wc[i][k])
        if (bid < 64) {
            const int tr = bid >> 2, tc = bid & 3;
            const int row0 = tr * 16, col0 = tc * 16;
            float acc[1][1] = {};
            gemm_nn<16, 16>(a_s, b_s, g_eh + row0 * HID, HID,
                            w_c + col0, CAUS, HID, acc);
            const int r = row0 + ty;
            const int kc = col0 + tx;
            g_c[r * CAUS + kc] -= 0.1f * acc[0][0];
        }
        grid_sync();
    }
}

// ---------------------------------------------------------------------------
// Launch: single kernel node, graph-capturable, no allocation.
// Inputs (metadata order): x, c_init, h_init, w_o, b_o, w_c, w_r, b_r
// ---------------------------------------------------------------------------
extern "C" void kernel_launch(void* const* d_in, const int* in_sizes, int n_in,
                              void* d_out, int out_size) {
    const float* x      = (const float*)d_in[0];
    const float* c_init = (const float*)d_in[1];
    const float* h_init = (const float*)d_in[2];
    const float* w_o    = (const float*)d_in[3];
    const float* b_o    = (const float*)d_in[4];
    const float* w_c    = (const float*)d_in[5];
    const float* w_r    = (const float*)d_in[6];
    const float* b_r    = (const float*)d_in[7];
    float* out = (float*)d_out;

    pc_rnn_kernel<<<GRID, NTHREADS>>>(x, c_init, h_init, w_o, b_o, w_c, w_r, b_r, out);
}

// round 8
// speedup vs baseline: 1.2297x; 1.2287x over previous
#include <cuda_runtime.h>

// ---------------------------------------------------------------------------
// PC_RNN_HC_A round 7: persistent kernel, grid barrier, GEMMs with
// A-operand via broadcast LDG, cp.async double-buffered weight tiles,
// conflict-free smem (stride 68), pre-transposed Wo/Wc for phases C/D.
// ---------------------------------------------------------------------------

#define GRID      128
#define NTHREADS  256

#define SEQ   512
#define BATCH 256
#define OUTD  256
#define CAUS  64
#define HID   512

#define SB 68   // smem stride (floats) for B tiles: 68 mod 32 = 4 -> conflict-free
                // LDS.128 within 8-lane phases; rows stay 16B aligned.

// Persistent state (device globals: allocation is forbidden)
__device__ float g_h  [BATCH * HID];
__device__ float g_th [BATCH * HID];
__device__ float g_hp [BATCH * HID];
__device__ float g_tp [BATCH * HID];
__device__ float g_eh [BATCH * HID];
__device__ float g_err[BATCH * OUTD];
__device__ float g_c  [BATCH * CAUS];
__device__ float g_woT[HID * OUTD];   // woT[i][o] = w_o[o][i]
__device__ float g_wcT[CAUS * HID];   // wcT[c][i] = w_c[i][c]

__device__ unsigned g_bar_count;      // zero at module load
__device__ unsigned g_bar_gen;

// ---------------------------------------------------------------------------
// Grid-wide barrier (monotone generation; replay-safe). grid <= SM count so
// all CTAs are resident and spinning is deadlock-free.
// ---------------------------------------------------------------------------
__device__ __forceinline__ void grid_sync() {
    __syncthreads();
    if (threadIdx.x == 0) {
        volatile unsigned* genp = &g_bar_gen;
        unsigned my = *genp;
        __threadfence();
        unsigned prev = atomicAdd(&g_bar_count, 1u);
        if (prev == GRID - 1u) {
            g_bar_count = 0u;
            __threadfence();
            atomicExch(&g_bar_gen, my + 1u);
        } else {
            while (*genp == my) { }
            __threadfence();
        }
    }
    __syncthreads();
}

// ---------------------------------------------------------------------------
// cp.async helpers
// ---------------------------------------------------------------------------
__device__ __forceinline__ void cp_async16(float* s, const float* g) {
    unsigned sa = (unsigned)__cvta_generic_to_shared(s);
    asm volatile("cp.async.ca.shared.global [%0], [%1], 16;" :: "r"(sa), "l"(g));
}
__device__ __forceinline__ void cp_commit() {
    asm volatile("cp.async.commit_group;");
}
__device__ __forceinline__ void cp_wait0() {
    asm volatile("cp.async.wait_group 0;");
}

// Fill one B tile: TN rows x 64 k, row-major k-major source (ldb), stride SB.
template<int TN>
__device__ __forceinline__ void fill_b(float* bs, const float* __restrict__ B,
                                       int ldb, int k0) {
    const int tid = threadIdx.x;
#pragma unroll
    for (int it = 0; it < (TN * 16) / NTHREADS; it++) {
        int idx = tid + it * NTHREADS;
        int n   = idx >> 4;
        int k4  = idx & 15;
        cp_async16(bs + n * SB + k4 * 4, B + n * ldb + k0 + k4 * 4);
    }
}

// ---------------------------------------------------------------------------
// NT GEMM: acc[im][in] += sum_k A[ty+16im][k] * B[tx+16in][k]
// A read directly from global (broadcast within warp: lanes sharing ty hit the
// same row). B staged through cp.async double-buffered smem.
// Thread layout: tx = tid&15 (cols), ty = tid>>4 (rows).
// ---------------------------------------------------------------------------
template<int RM, int RN>
__device__ __forceinline__ void gemm_nt(float* bbuf,
                                        const float* __restrict__ A, int lda,
                                        const float* __restrict__ B, int ldb,
                                        int ktiles,
                                        float (&acc)[RM][RN]) {
    constexpr int TN = 16 * RN;
    const int tx = threadIdx.x & 15, ty = threadIdx.x >> 4;

    __syncthreads();                 // protect bbuf from previous phase's reads
    fill_b<TN>(bbuf, B, ldb, 0);
    cp_commit();

    const float* Ar[RM];
#pragma unroll
    for (int im = 0; im < RM; im++) Ar[im] = A + (ty + 16 * im) * lda;

    int buf = 0;
    for (int kt = 0; kt < ktiles; kt++) {
        cp_wait0();
        __syncthreads();
        if (kt + 1 < ktiles) {
            fill_b<TN>(bbuf + (buf ^ 1) * TN * SB, B, ldb, (kt + 1) * 64);
            cp_commit();
        }
        const float* bs = bbuf + buf * TN * SB;
        const int kb = kt * 64;
#pragma unroll
        for (int k4 = 0; k4 < 16; k4++) {
            float4 av[RM], bv[RN];
#pragma unroll
            for (int im = 0; im < RM; im++)
                av[im] = *reinterpret_cast<const float4*>(Ar[im] + kb + k4 * 4);
#pragma unroll
            for (int in = 0; in < RN; in++)
                bv[in] = *reinterpret_cast<const float4*>(bs + (tx + 16 * in) * SB + k4 * 4);
#pragma unroll
            for (int im = 0; im < RM; im++)
#pragma unroll
                for (int in = 0; in < RN; in++) {
                    acc[im][in] += av[im].x * bv[in].x;
                    acc[im][in] += av[im].y * bv[in].y;
                    acc[im][in] += av[im].z * bv[in].z;
                    acc[im][in] += av[im].w * bv[in].w;
                }
        }
        buf ^= 1;
    }
}

// ---------------------------------------------------------------------------
// Phase D dot kernel: 128 compute threads (tid<128), each computes
// dot(A_row[0..511], wcT_col_row[0..511]). B (16 rows of wcT) double-buffered.
// All 256 threads participate in fills and syncs.
// ---------------------------------------------------------------------------
__device__ __forceinline__ float gemm_d(float* bbuf,
                                        const float* __restrict__ Arow,
                                        const float* __restrict__ B) {
    const int tid = threadIdx.x;
    __syncthreads();
    fill_b<16>(bbuf, B, HID, 0);
    cp_commit();
    float acc = 0.0f;
    int buf = 0;
    for (int kt = 0; kt < 8; kt++) {
        cp_wait0();
        __syncthreads();
        if (kt < 7) {
            fill_b<16>(bbuf + (buf ^ 1) * 16 * SB, B, HID, (kt + 1) * 64);
            cp_commit();
        }
        if (tid < 128) {
            const float* bs = bbuf + buf * 16 * SB;
            const int tx = tid & 15;
            const int kb = kt * 64;
#pragma unroll
            for (int k4 = 0; k4 < 16; k4++) {
                float4 a = *reinterpret_cast<const float4*>(Arow + kb + k4 * 4);
                float4 b = *reinterpret_cast<const float4*>(bs + tx * SB + k4 * 4);
                acc += a.x * b.x + a.y * b.y + a.z * b.z + a.w * b.w;
            }
        }
        buf ^= 1;
    }
    return acc;
}

// ---------------------------------------------------------------------------
// Main persistent kernel
// ---------------------------------------------------------------------------
__global__ void __launch_bounds__(NTHREADS, 1)
pc_rnn_kernel(const float* __restrict__ x,
              const float* __restrict__ c_init,
              const float* __restrict__ h_init,
              const float* __restrict__ w_o,
              const float* __restrict__ b_o,
              const float* __restrict__ w_c,
              const float* __restrict__ w_r,
              const float* __restrict__ b_r,
              float* __restrict__ out) {
    __shared__ float bbuf[2 * 32 * SB];   // 17408 B: double buffer, max TN=32

    const int bid = blockIdx.x;
    const int tid = threadIdx.x;
    const int tx  = tid & 15, ty = tid >> 4;
    const int gtid = bid * NTHREADS + tid;
    const int gstride = GRID * NTHREADS;

    // ---- init state + weight transposes (fresh every launch/replay) ----
    for (int i = gtid; i < BATCH * HID; i += gstride) {
        float h = h_init[i];
        g_h[i]  = h;
        g_th[i] = tanhf(h);
    }
    for (int i = gtid; i < BATCH * CAUS; i += gstride)
        g_c[i] = c_init[i];
    for (int i = gtid; i < HID * OUTD; i += gstride) {   // woT[i][o] = w_o[o][i]
        int hh = i >> 8, o = i & (OUTD - 1);
        g_woT[i] = w_o[o * HID + hh];
    }
    for (int i = gtid; i < CAUS * HID; i += gstride) {   // wcT[c][i] = w_c[i][c]
        int c = i >> 9, hh = i & (HID - 1);
        g_wcT[i] = w_c[hh * CAUS + c];
    }
    grid_sync();

    for (int t = 0; t < SEQ; t++) {
        // ---- Phase A: h_prior = 0.9*h + 0.1*(th@Wr^T + c@Wc^T + b_r); tp=tanh ----
        // 256x512 out, 32x32 tiles, 8x16 grid = 128 CTAs
        {
            const int row0 = (bid >> 4) * 32, col0 = (bid & 15) * 32;
            float acc[2][2] = {};
            gemm_nt<2, 2>(bbuf, g_th + row0 * HID, HID,
                          w_r + col0 * HID, HID, HID / 64, acc);
            gemm_nt<2, 2>(bbuf, g_c + row0 * CAUS, CAUS,
                          w_c + col0 * CAUS, CAUS, 1, acc);
#pragma unroll
            for (int im = 0; im < 2; im++)
#pragma unroll
                for (int in = 0; in < 2; in++) {
                    int r   = row0 + ty + 16 * im;
                    int ci  = col0 + tx + 16 * in;
                    int idx = r * HID + ci;
                    float hp = 0.9f * g_h[idx] + 0.1f * (acc[im][in] + b_r[ci]);
                    g_hp[idx] = hp;
                    g_tp[idx] = tanhf(hp);
                }
        }
        grid_sync();

        // ---- Phase B: err = tp@Wo^T + b_o - x_t  (streamed to out too) ----
        // 256x256 out, 16x32 tiles, 16x8 grid = 128 CTAs
        {
            const int row0 = (bid >> 3) * 16, col0 = (bid & 7) * 32;
            float acc[1][2] = {};
            gemm_nt<1, 2>(bbuf, g_tp + row0 * HID, HID,
                          w_o + col0 * HID, HID, HID / 64, acc);
            const int r = row0 + ty;
#pragma unroll
            for (int in = 0; in < 2; in++) {
                int o  = col0 + tx + 16 * in;
                int xi = (t * BATCH + r) * OUTD + o;
                float e = acc[0][in] + b_o[o] - x[xi];
                g_err[r * OUTD + o] = e;
                out[xi] = e;
            }
        }
        grid_sync();

        // ---- Phase C: g = err@Wo (via woT); eh = 0.1*(1-tp^2)*g; h_post ----
        // 256x512 out, 32x32 tiles, 8x16 grid = 128 CTAs
        {
            const int row0 = (bid >> 4) * 32, col0 = (bid & 15) * 32;
            float acc[2][2] = {};
            gemm_nt<2, 2>(bbuf, g_err + row0 * OUTD, OUTD,
                          g_woT + col0 * OUTD, OUTD, OUTD / 64, acc);
#pragma unroll
            for (int im = 0; im < 2; im++)
#pragma unroll
                for (int in = 0; in < 2; in++) {
                    int r   = row0 + ty + 16 * im;
                    int ci  = col0 + tx + 16 * in;
                    int idx = r * HID + ci;
                    float tp = g_tp[idx];
                    float eh = 0.1f * (1.0f - tp * tp) * acc[im][in];
                    float hpost = g_hp[idx] - eh;
                    g_eh[idx] = eh;
                    g_h[idx]  = hpost;
                    g_th[idx] = tanhf(hpost);
                }
        }
        grid_sync();

        // ---- Phase D: c -= 0.1 * (eh @ Wc)  (via wcT) ----
        // 256x64 out, 8x16 tiles, 32x4 grid = 128 CTAs; 128 compute threads
        {
            const int row0 = (bid >> 2) * 8, col0 = (bid & 3) * 16;
            const int r = row0 + (ty & 7);               // valid for tid<128
            float a = gemm_d(bbuf, g_eh + r * HID, g_wcT + col0 * HID);
            if (tid < 128)
                g_c[r * CAUS + col0 + tx] -= 0.1f * a;
        }
        grid_sync();
    }
}

// ---------------------------------------------------------------------------
// Launch: single graph-capturable kernel node, no allocation.
// Inputs (metadata order): x, c_init, h_init, w_o, b_o, w_c, w_r, b_r
// ---------------------------------------------------------------------------
extern "C" void kernel_launch(void* const* d_in, const int* in_sizes, int n_in,
                              void* d_out, int out_size) {
    const float* x      = (const float*)d_in[0];
    const float* c_init = (const float*)d_in[1];
    const float* h_init = (const float*)d_in[2];
    const float* w_o    = (const float*)d_in[3];
    const float* b_o    = (const float*)d_in[4];
    const float* w_c    = (const float*)d_in[5];
    const float* w_r    = (const float*)d_in[6];
    const float* b_r    = (const float*)d_in[7];
    float* out = (float*)d_out;

    pc_rnn_kernel<<<GRID, NTHREADS>>>(x, c_init, h_init, w_o, b_o, w_c, w_r, b_r, out);
}